// round 8
// baseline (speedup 1.0000x reference)
#include <cuda_runtime.h>
#include <math.h>
#include <stdint.h>

#define S    64
#define NF   196608
#define HD   128
#define K2   (2*NF)
#define NSUB (NF/32)   // 6144 k-subtiles of 32
#define CL   8         // scan cluster size

// Scratch (device globals — no allocation allowed)
__device__ float g_U[S*HD];     // U[t*HD+h] = (W_z @ z_t)[h]
__device__ float g_M[HD*HD];    // g_M[h*HD+c] = (W_p @ fc2_w)[h][c] (row-major)
__device__ float g_v[HD];       // W_p @ fc2_b
__device__ float g_w0[HD];      // W_p @ prev_gen0
__device__ float g_H2T[HD*S];   // h2 states, TRANSPOSED: g_H2T[j*S + t]

__device__ __forceinline__ float sigm(float x) { return 1.f / (1.f + expf(-x)); }

// ---- f32x2 packed fp32 helpers (PTX-only; ptxas won't auto-fuse) ----
__device__ __forceinline__ unsigned long long pack2(float a) {
    unsigned long long r;
    asm("mov.b64 %0, {%1, %1};" : "=l"(r) : "f"(a));
    return r;
}
__device__ __forceinline__ void fma2(unsigned long long& d, unsigned long long a, unsigned long long b) {
    asm("fma.rn.f32x2 %0, %1, %2, %0;" : "+l"(d) : "l"(a), "l"(b));
}
__device__ __forceinline__ float lo2(unsigned long long v) { return __uint_as_float((unsigned)(v & 0xffffffffu)); }
__device__ __forceinline__ float hi2(unsigned long long v) { return __uint_as_float((unsigned)(v >> 32)); }

// ---- cluster / DSMEM / mbarrier helpers ----
__device__ __forceinline__ uint32_t smem_u32(const void* p) {
    uint32_t a;
    asm("{ .reg .u64 t; cvta.to.shared.u64 t, %1; cvt.u32.u64 %0, t; }" : "=r"(a) : "l"(p));
    return a;
}
__device__ __forceinline__ uint32_t ctarank() {
    uint32_t r; asm("mov.u32 %0, %%cluster_ctarank;" : "=r"(r)); return r;
}
__device__ __forceinline__ uint32_t mapa_u32(uint32_t addr, uint32_t rank) {
    uint32_t r; asm("mapa.shared::cluster.u32 %0, %1, %2;" : "=r"(r) : "r"(addr), "r"(rank));
    return r;
}
__device__ __forceinline__ void st_cluster(uint32_t addr, float v) {
    asm volatile("st.shared::cluster.f32 [%0], %1;" :: "r"(addr), "f"(v) : "memory");
}
__device__ __forceinline__ void mbar_init(uint32_t addr, uint32_t count) {
    asm volatile("mbarrier.init.shared.b64 [%0], %1;" :: "r"(addr), "r"(count) : "memory");
}
// release-arrive at cluster scope on a (possibly remote) cluster smem barrier:
// orders this thread's prior st.shared::cluster stores before the arrival.
__device__ __forceinline__ void mbar_arrive_cluster(uint32_t addr) {
    asm volatile("mbarrier.arrive.release.cluster.shared::cluster.b64 _, [%0];"
                 :: "r"(addr) : "memory");
}
// acquire-wait (cluster scope) on local barrier, spin on try_wait.
__device__ __forceinline__ void mbar_wait_cluster(uint32_t addr, uint32_t parity) {
    asm volatile(
        "{\n\t.reg .pred P;\n\t"
        "W%=:\n\t"
        "mbarrier.try_wait.parity.acquire.cluster.shared::cta.b64 P, [%0], %1;\n\t"
        "@P bra D%=;\n\t"
        "bra W%=;\n\t"
        "D%=:\n\t}"
        :: "r"(addr), "r"(parity) : "memory");
}
#define CLUSTER_BAR() do { \
    asm volatile("barrier.cluster.arrive.aligned;" ::: "memory"); \
    asm volatile("barrier.cluster.wait.aligned;"   ::: "memory"); \
} while (0)

// ---------------- zero the atomic accumulators ----------------
__global__ void k_zero() {
    int n = S*HD + HD*HD + 2*HD;
    for (int i = blockIdx.x*blockDim.x + threadIdx.x; i < n; i += gridDim.x*blockDim.x) {
        if (i < S*HD)               g_U[i] = 0.f;
        else if (i < S*HD + HD*HD)  g_M[i - S*HD] = 0.f;
        else if (i < S*HD + HD*HD + HD) g_v[i - S*HD - HD*HD] = 0.f;
        else                        g_w0[i - S*HD - HD*HD - HD] = 0.f;
    }
}

// ------- GEMM 1 (f32x2): U[128 x 64] = W_z[128,K] * Z^T[K,64] (split-K, NT) -------
// Rows paired (packed accumulators along M); A tile stored k-major-transposed so
// row pairs are contiguous for LDS.64; B (Zs) scalar broadcast-packed.
__global__ void __launch_bounds__(256, 2) k_gemm_u(const float* __restrict__ fc1w,
                                                   const float* __restrict__ z) {
    __shared__ __align__(16) float AsT[32*130];   // [kk][row], pad 2
    __shared__ float Zs[64*33];                   // [t][kk],  pad 1
    int tid = threadIdx.x;
    int ty = tid >> 4, tx = tid & 15;             // ty<16, tx<16
    unsigned long long acc2[4][4];                // 4 row-pairs x 4 cols
    #pragma unroll
    for (int r = 0; r < 4; r++)
        #pragma unroll
        for (int c = 0; c < 4; c++) acc2[r][c] = 0ull;

    for (int st = blockIdx.x; st < NSUB; st += gridDim.x) {
        int kb = st << 5;
        for (int idx = tid; idx < 128*32; idx += 256) {
            int row = idx >> 5, kk = idx & 31;
            AsT[kk*130 + row] = fc1w[row*K2 + kb + kk];
        }
        for (int idx = tid; idx < 64*32; idx += 256) {
            int t = idx >> 5, kk = idx & 31;
            Zs[t*33 + kk] = z[t*NF + kb + kk];
        }
        __syncthreads();
        #pragma unroll
        for (int kk = 0; kk < 32; kk++) {
            unsigned long long pa[4];
            #pragma unroll
            for (int r = 0; r < 4; r++)
                pa[r] = *(const unsigned long long*)(&AsT[kk*130 + 2*ty + 32*r]);
            #pragma unroll
            for (int c = 0; c < 4; c++) {
                unsigned long long pb = pack2(Zs[(tx + 16*c)*33 + kk]);
                #pragma unroll
                for (int r = 0; r < 4; r++) fma2(acc2[r][c], pa[r], pb);
            }
        }
        __syncthreads();
    }
    #pragma unroll
    for (int r = 0; r < 4; r++)
        #pragma unroll
        for (int c = 0; c < 4; c++) {
            int row = 2*ty + 32*r, col = tx + 16*c;
            atomicAdd(&g_U[col*HD + row],     lo2(acc2[r][c]));
            atomicAdd(&g_U[col*HD + row + 1], hi2(acc2[r][c]));
        }
}

// ------- GEMM 2 (f32x2): M[128x128] = W_p[128,K] * fc2_w[K,128] (+ W_p@fc2_b, W_p@pg0) -------
__global__ void __launch_bounds__(256, 2) k_gemm_m(const float* __restrict__ fc1w,
                                                   const float* __restrict__ fc2w,
                                                   const float* __restrict__ fc2b,
                                                   const float* __restrict__ pg0) {
    __shared__ float As[128*33];
    __shared__ __align__(16) float Bs[32*128];
    __shared__ float Es[64];
    int tid = threadIdx.x;
    int ty = tid >> 4, tx = tid & 15;
    int erow = tid & 127, ewhich = tid >> 7;
    unsigned long long acc2[8][4];
    float accE = 0.f;
    #pragma unroll
    for (int r = 0; r < 8; r++)
        #pragma unroll
        for (int c = 0; c < 4; c++) acc2[r][c] = 0ull;

    for (int st = blockIdx.x; st < NSUB; st += gridDim.x) {
        int kb = st << 5;
        for (int idx = tid; idx < 128*32; idx += 256) {
            int row = idx >> 5, kk = idx & 31;
            As[row*33 + kk] = fc1w[row*K2 + NF + kb + kk];
        }
        for (int idx = tid; idx < 32*128; idx += 256) {
            int kk = idx >> 7, c = idx & 127;
            Bs[kk*128 + c] = fc2w[(kb + kk)*128 + c];
        }
        if (tid < 64) Es[tid] = (tid < 32) ? fc2b[kb + tid] : pg0[kb + (tid - 32)];
        __syncthreads();
        #pragma unroll
        for (int kk = 0; kk < 32; kk++) {
            unsigned long long pa[8];
            #pragma unroll
            for (int r = 0; r < 8; r++) pa[r] = pack2(As[(ty + 16*r)*33 + kk]);
            #pragma unroll
            for (int c2 = 0; c2 < 4; c2++) {
                unsigned long long pb = *(const unsigned long long*)(&Bs[kk*128 + 2*tx + 32*c2]);
                #pragma unroll
                for (int r = 0; r < 8; r++) fma2(acc2[r][c2], pa[r], pb);
            }
            accE += As[erow*33 + kk] * Es[ewhich*32 + kk];
        }
        __syncthreads();
    }
    #pragma unroll
    for (int r = 0; r < 8; r++)
        #pragma unroll
        for (int c2 = 0; c2 < 4; c2++) {
            int col = 2*tx + 32*c2;
            atomicAdd(&g_M[(ty + 16*r)*HD + col],     lo2(acc2[r][c2]));
            atomicAdd(&g_M[(ty + 16*r)*HD + col + 1], hi2(acc2[r][c2]));
        }
    atomicAdd(ewhich ? &g_w0[erow] : &g_v[erow], accE);
}

// ---------------- Phase 2: cluster-resident recurrent scan (v3) ----------------
// 8-CTA cluster. Per CTA: 64 gate rows per LSTM resident in SMEM, PLUS full M
// (64KB) + full U_t (L2-prefetched) + full bias vectors, so the x-phase runs
// entirely locally (no x broadcast, no barrier). Only 2 syncs/step remain
// (h1, h2 broadcasts), done with DSMEM stores + mbarrier release-arrive /
// acquire-wait (TRYWAIT ~60-90cyc) instead of barrier.cluster (~490cyc).
// Convention: values of step t live in buffer (t&1); initial states in buffer 1.
#define OFS_WI1 0
#define OFS_WH1 8192
#define OFS_WI2 16384
#define OFS_WH2 24576
#define OFS_M   32768          /* full 128x128, row-major */
#define OFS_U   49152          /* 2 x 128, double-buffered, full */
#define OFS_X   49408          /* full 128, local */
#define OFS_H1  49536          /* 2 x 128 */
#define OFS_H2  49792          /* 2 x 128 */
#define OFS_G   50048          /* 64 */
#define OFS_B1  50112
#define OFS_B2  50176
#define OFS_XB  50240          /* full 128: fc1b+v  */
#define OFS_XB0 50368          /* full 128: fc1b+w0 */
#define OFS_C1  50496
#define OFS_C2  50512
#define OFS_MB  50528          /* 2 mbarriers (u64 each); 50528*4 % 8 == 0 */
#define SCAN_SMEM_FLOATS 50536
#define SCAN_SMEM_BYTES  (SCAN_SMEM_FLOATS*4)

__global__ void __launch_bounds__(256, 1) __cluster_dims__(CL, 1, 1)
k_scan(const float* __restrict__ h1_in, const float* __restrict__ c1_in,
       const float* __restrict__ h2_in, const float* __restrict__ c2_in,
       const float* __restrict__ fc1b,
       const float* __restrict__ wih1, const float* __restrict__ whh1,
       const float* __restrict__ bih1, const float* __restrict__ bhh1,
       const float* __restrict__ wih2, const float* __restrict__ whh2,
       const float* __restrict__ bih2, const float* __restrict__ bhh2,
       float* __restrict__ out, int out_size)
{
    extern __shared__ __align__(16) float sm[];
    const int tid  = threadIdx.x;
    const int warp = tid >> 5, lane = tid & 31;
    const uint32_t rank = ctarank();
    const uint32_t sbase = smem_u32(sm);
    const uint32_t bar1 = sbase + OFS_MB*4u;
    const uint32_t bar2 = sbase + OFS_MB*4u + 8u;

    // ---- resident loads (once) ----
    for (int idx = tid; idx < 64*128; idx += 256) {
        int l = idx >> 7, k = idx & 127;
        int gr = ((l >> 4) << 7) + (int)rank*16 + (l & 15);   // gate*128 + elem
        sm[OFS_WI1 + idx] = wih1[gr*HD + k];
        sm[OFS_WH1 + idx] = whh1[gr*HD + k];
        sm[OFS_WI2 + idx] = wih2[gr*HD + k];
        sm[OFS_WH2 + idx] = whh2[gr*HD + k];
    }
    for (int idx = tid; idx < HD*HD; idx += 256) sm[OFS_M + idx] = g_M[idx];
    if (tid < 64) {
        int gr = ((tid >> 4) << 7) + (int)rank*16 + (tid & 15);
        sm[OFS_B1 + tid] = bih1[gr] + bhh1[gr];
        sm[OFS_B2 + tid] = bih2[gr] + bhh2[gr];
    }
    if (tid < HD) {
        sm[OFS_XB  + tid] = fc1b[tid] + g_v[tid];
        sm[OFS_XB0 + tid] = fc1b[tid] + g_w0[tid];
        sm[OFS_U   + tid] = g_U[tid];            // U_0 into buffer 0
        sm[OFS_H1 + HD + tid] = h1_in[tid];      // initial states -> buffer 1
        sm[OFS_H2 + HD + tid] = h2_in[tid];
    }
    if (tid < 16) {
        int e = (int)rank*16 + tid;
        sm[OFS_C1 + tid] = c1_in[e];
        sm[OFS_C2 + tid] = c2_in[e];
    }
    if (tid == 0) { mbar_init(bar1, 128); mbar_init(bar2, 128); }
    __syncthreads();
    CLUSTER_BAR();   // barriers + resident data visible cluster-wide

    for (int t = 0; t < S; t++) {
        const int p = t & 1;

        // ---- X phase (fully local): x = relu(U_t + M@h2_{t-1} + fc1b + v) ----
        if (t == 0) {
            if (tid < HD) sm[OFS_X + tid] = fmaxf(sm[OFS_U + tid] + sm[OFS_XB0 + tid], 0.f);
        } else {
            float4 hv = ((const float4*)(sm + OFS_H2 + (p^1)*HD))[lane];
            #pragma unroll
            for (int i = 0; i < 16; i++) {
                int r = warp*16 + i;
                float4 m = ((const float4*)(sm + OFS_M + r*HD))[lane];
                float pd = m.x*hv.x + m.y*hv.y + m.z*hv.z + m.w*hv.w;
                #pragma unroll
                for (int off = 16; off; off >>= 1) pd += __shfl_xor_sync(0xffffffffu, pd, off);
                if (lane == 0)
                    sm[OFS_X + r] = fmaxf(pd + sm[OFS_U + p*HD + r] + sm[OFS_XB + r], 0.f);
            }
        }
        __syncthreads();

        // prefetch U_{t+1} (L2-resident; consumed after next step's syncthreads)
        if (t < S-1 && tid < HD) sm[OFS_U + (p^1)*HD + tid] = g_U[(t+1)*HD + tid];

        // ---- LSTM1: 64 rows/CTA; reads full x (local) + h1[t-1] ----
        {
            float4 xv = ((const float4*)(sm + OFS_X))[lane];
            float4 hv = ((const float4*)(sm + OFS_H1 + (p^1)*HD))[lane];
            #pragma unroll
            for (int i = 0; i < 8; i++) {
                int l = warp*8 + i;
                float4 wi = ((const float4*)(sm + OFS_WI1 + l*HD))[lane];
                float4 wh = ((const float4*)(sm + OFS_WH1 + l*HD))[lane];
                float pd = wi.x*xv.x + wi.y*xv.y + wi.z*xv.z + wi.w*xv.w
                         + wh.x*hv.x + wh.y*hv.y + wh.z*hv.z + wh.w*hv.w;
                #pragma unroll
                for (int off = 16; off; off >>= 1) pd += __shfl_xor_sync(0xffffffffu, pd, off);
                if (lane == 0) sm[OFS_G + l] = pd + sm[OFS_B1 + l];
            }
        }
        __syncthreads();
        if (tid < 16) {
            float gi = sm[OFS_G + tid],      gf = sm[OFS_G + 16 + tid];
            float gg = sm[OFS_G + 32 + tid], go = sm[OFS_G + 48 + tid];
            float c = sigm(gf)*sm[OFS_C1 + tid] + sigm(gi)*tanhf(gg);
            sm[OFS_C1 + tid] = c;
            sm[OFS_H1 + p*HD + (int)rank*16 + tid] = sigm(go)*tanhf(c);
        }
        __syncthreads();
        if (tid < 128) {   // broadcast own h1 slice: 16 elems x 8 dests
            int e = (int)rank*16 + (tid >> 3);
            uint32_t d = (uint32_t)(tid & 7);
            st_cluster(mapa_u32(sbase + (uint32_t)(OFS_H1 + p*HD + e)*4u, d),
                       sm[OFS_H1 + p*HD + e]);
            mbar_arrive_cluster(mapa_u32(bar1, d));
        }
        mbar_wait_cluster(bar1, (uint32_t)p);

        // ---- LSTM2: input h1[t] (just delivered), hidden h2[t-1] ----
        {
            float4 xv = ((const float4*)(sm + OFS_H1 + p*HD))[lane];
            float4 hv = ((const float4*)(sm + OFS_H2 + (p^1)*HD))[lane];
            #pragma unroll
            for (int i = 0; i < 8; i++) {
                int l = warp*8 + i;
                float4 wi = ((const float4*)(sm + OFS_WI2 + l*HD))[lane];
                float4 wh = ((const float4*)(sm + OFS_WH2 + l*HD))[lane];
                float pd = wi.x*xv.x + wi.y*xv.y + wi.z*xv.z + wi.w*xv.w
                         + wh.x*hv.x + wh.y*hv.y + wh.z*hv.z + wh.w*hv.w;
                #pragma unroll
                for (int off = 16; off; off >>= 1) pd += __shfl_xor_sync(0xffffffffu, pd, off);
                if (lane == 0) sm[OFS_G + l] = pd + sm[OFS_B2 + l];
            }
        }
        __syncthreads();
        if (tid < 16) {
            float gi = sm[OFS_G + tid],      gf = sm[OFS_G + 16 + tid];
            float gg = sm[OFS_G + 32 + tid], go = sm[OFS_G + 48 + tid];
            float c = sigm(gf)*sm[OFS_C2 + tid] + sigm(gi)*tanhf(gg);
            sm[OFS_C2 + tid] = c;
            float h = sigm(go)*tanhf(c);
            int e = (int)rank*16 + tid;
            sm[OFS_H2 + p*HD + e] = h;
            g_H2T[e*S + t] = h;                  // transposed for k_out
        }
        __syncthreads();
        if (tid < 128) {
            int e = (int)rank*16 + (tid >> 3);
            uint32_t d = (uint32_t)(tid & 7);
            st_cluster(mapa_u32(sbase + (uint32_t)(OFS_H2 + p*HD + e)*4u, d),
                       sm[OFS_H2 + p*HD + e]);
            mbar_arrive_cluster(mapa_u32(bar2, d));
        }
        mbar_wait_cluster(bar2, (uint32_t)p);
    }

    // step 63 lives in buffer 1; c slices are CTA-local
    if (out_size >= S*NF + 4*HD && tid < 16) {
        int e = (int)rank*16 + tid;
        out[S*NF + 0*HD + e] = sm[OFS_H1 + HD + e];
        out[S*NF + 1*HD + e] = sm[OFS_C1 + tid];
        out[S*NF + 2*HD + e] = sm[OFS_H2 + HD + e];
        out[S*NF + 3*HD + e] = sm[OFS_C2 + tid];
    }
    __syncthreads();
    CLUSTER_BAR();   // no CTA exits while peers may still store into its smem
}

// ------- GEMM 3 (f32x2): out[t,k] = fc2_w[k,:] . h2_t + fc2_b[k] + y[t,k] -------
__global__ void __launch_bounds__(256) k_out(const float* __restrict__ fc2w,
                                             const float* __restrict__ fc2b,
                                             const float* __restrict__ y,
                                             float* __restrict__ out) {
    __shared__ __align__(16) float H2T[HD*S];
    int tid = threadIdx.x;
    for (int i = tid; i < HD*S; i += 256) H2T[i] = g_H2T[i];
    __syncthreads();

    int k = blockIdx.x*256 + tid;
    const float4* w4 = (const float4*)(fc2w + k*HD);
    unsigned long long acc2[32];
    #pragma unroll
    for (int i = 0; i < 32; i++) acc2[i] = 0ull;

    #pragma unroll 2
    for (int j4 = 0; j4 < 32; j4++) {
        float4 w = w4[j4];
        float wc[4] = {w.x, w.y, w.z, w.w};
        #pragma unroll
        for (int cc = 0; cc < 4; cc++) {
            unsigned long long pw = pack2(wc[cc]);
            int j = j4*4 + cc;
            const ulonglong2* hp = (const ulonglong2*)(H2T + j*S);
            #pragma unroll
            for (int tq = 0; tq < 16; tq++) {
                ulonglong2 hh = hp[tq];
                fma2(acc2[2*tq],     pw, hh.x);
                fma2(acc2[2*tq + 1], pw, hh.y);
            }
        }
    }
    float b = fc2b[k];
    #pragma unroll 4
    for (int i = 0; i < 32; i++) {
        int t0 = 2*i;
        out[t0*NF + k]       = lo2(acc2[i]) + b + y[t0*NF + k];
        out[(t0 + 1)*NF + k] = hi2(acc2[i]) + b + y[(t0 + 1)*NF + k];
    }
}

// ---------------- launcher ----------------
extern "C" void kernel_launch(void* const* d_in, const int* in_sizes, int n_in,
                              void* d_out, int out_size) {
    const float* z    = (const float*)d_in[0];
    const float* y    = (const float*)d_in[1];
    const float* pg0  = (const float*)d_in[2];
    const float* h1   = (const float*)d_in[3];
    const float* c1   = (const float*)d_in[4];
    const float* h2   = (const float*)d_in[5];
    const float* c2   = (const float*)d_in[6];
    const float* fc1w = (const float*)d_in[7];
    const float* fc1b = (const float*)d_in[8];
    const float* wih1 = (const float*)d_in[9];
    const float* whh1 = (const float*)d_in[10];
    const float* bih1 = (const float*)d_in[11];
    const float* bhh1 = (const float*)d_in[12];
    const float* wih2 = (const float*)d_in[13];
    const float* whh2 = (const float*)d_in[14];
    const float* bih2 = (const float*)d_in[15];
    const float* bhh2 = (const float*)d_in[16];
    const float* fc2w = (const float*)d_in[17];
    const float* fc2b = (const float*)d_in[18];
    float* out = (float*)d_out;

    cudaFuncSetAttribute(k_scan, cudaFuncAttributeMaxDynamicSharedMemorySize, SCAN_SMEM_BYTES);

    k_zero<<<32, 256>>>();
    k_gemm_u<<<296, 256>>>(fc1w, z);
    k_gemm_m<<<296, 256>>>(fc1w, fc2w, fc2b, pg0);
    k_scan<<<CL, 256, SCAN_SMEM_BYTES>>>(h1, c1, h2, c2, fc1b,
                                         wih1, whh1, bih1, bhh1,
                                         wih2, whh2, bih2, bhh2,
                                         out, out_size);
    k_out<<<768, 256>>>(fc2w, fc2b, y, out);
}

// round 9
// speedup vs baseline: 1.2156x; 1.2156x over previous
#include <cuda_runtime.h>
#include <cuda_bf16.h>
#include <math.h>
#include <stdint.h>

#define S    64
#define NF   196608
#define HD   128
#define K2   (2*NF)
#define CL   8         // scan cluster size

// mma GEMM config
#define G_CTAS 384
#define KPC    512          // k per CTA (384*512 = 196608)
#define KC     64           // k chunk
#define NCHUNK (KPC/KC)     // 8
#define AST    72           // smem row stride in bf16 (pad: conflict-free frag loads)

// Scratch (device globals — no allocation allowed)
__device__ float g_U[S*HD];     // U[t*HD+h] = (W_z @ z_t)[h]
__device__ float g_M[HD*HD];    // g_M[h*HD+c] = (W_p @ fc2_w)[h][c] (row-major)
__device__ float g_v[HD];       // W_p @ fc2_b
__device__ float g_w0[HD];      // W_p @ prev_gen0
__device__ float g_H2T[HD*S];   // h2 states, TRANSPOSED: g_H2T[j*S + t]

__device__ __forceinline__ float sigm(float x) { return 1.f / (1.f + expf(-x)); }

// ---- f32x2 packed fp32 helpers (k_out) ----
__device__ __forceinline__ unsigned long long pack2(float a) {
    unsigned long long r;
    asm("mov.b64 %0, {%1, %1};" : "=l"(r) : "f"(a));
    return r;
}
__device__ __forceinline__ void fma2(unsigned long long& d, unsigned long long a, unsigned long long b) {
    asm("fma.rn.f32x2 %0, %1, %2, %0;" : "+l"(d) : "l"(a), "l"(b));
}
__device__ __forceinline__ float lo2(unsigned long long v) { return __uint_as_float((unsigned)(v & 0xffffffffu)); }
__device__ __forceinline__ float hi2(unsigned long long v) { return __uint_as_float((unsigned)(v >> 32)); }

// ---- cluster / DSMEM helpers (scan) ----
__device__ __forceinline__ uint32_t smem_u32(const void* p) {
    uint32_t a;
    asm("{ .reg .u64 t; cvta.to.shared.u64 t, %1; cvt.u32.u64 %0, t; }" : "=r"(a) : "l"(p));
    return a;
}
__device__ __forceinline__ uint32_t ctarank() {
    uint32_t r; asm("mov.u32 %0, %%cluster_ctarank;" : "=r"(r)); return r;
}
__device__ __forceinline__ uint32_t mapa_u32(uint32_t addr, uint32_t rank) {
    uint32_t r; asm("mapa.shared::cluster.u32 %0, %1, %2;" : "=r"(r) : "r"(addr), "r"(rank));
    return r;
}
__device__ __forceinline__ void st_cluster(uint32_t addr, float v) {
    asm volatile("st.shared::cluster.f32 [%0], %1;" :: "r"(addr), "f"(v) : "memory");
}
#define CLUSTER_BAR() do { \
    asm volatile("barrier.cluster.arrive.aligned;" ::: "memory"); \
    asm volatile("barrier.cluster.wait.aligned;"   ::: "memory"); \
} while (0)

// ---- bf16 split + mma helpers ----
__device__ __forceinline__ void split_bf2(float2 v, uint32_t& hi, uint32_t& lo) {
    __nv_bfloat16 hx = __float2bfloat16(v.x);
    __nv_bfloat16 hy = __float2bfloat16(v.y);
    float rx = v.x - __bfloat162float(hx);
    float ry = v.y - __bfloat162float(hy);
    __nv_bfloat162 h2(hx, hy);
    __nv_bfloat162 l2(__float2bfloat16(rx), __float2bfloat16(ry));
    hi = *(uint32_t*)&h2;
    lo = *(uint32_t*)&l2;
}
#define MMA_BF16(c, a, b0_, b1_) \
    asm volatile("mma.sync.aligned.m16n8k16.row.col.f32.bf16.bf16.f32 " \
        "{%0,%1,%2,%3}, {%4,%5,%6,%7}, {%8,%9}, {%0,%1,%2,%3};" \
        : "+f"((c)[0]), "+f"((c)[1]), "+f"((c)[2]), "+f"((c)[3]) \
        : "r"((a)[0]), "r"((a)[1]), "r"((a)[2]), "r"((a)[3]), "r"(b0_), "r"(b1_))

// ---------------- zero the atomic accumulators ----------------
__global__ void k_zero() {
    int n = S*HD + HD*HD + 2*HD;
    for (int i = blockIdx.x*blockDim.x + threadIdx.x; i < n; i += gridDim.x*blockDim.x) {
        if (i < S*HD)               g_U[i] = 0.f;
        else if (i < S*HD + HD*HD)  g_M[i - S*HD] = 0.f;
        else if (i < S*HD + HD*HD + HD) g_v[i - S*HD - HD*HD] = 0.f;
        else                        g_w0[i - S*HD - HD*HD - HD] = 0.f;
    }
}

// ------- GEMM 1 (bf16-split mma): U[128 x 64] = W_z[128,K] * Z^T[K,64] -------
// 3-term split (hi*hi + hi*lo + lo*hi) ~ fp32 precision. Split-K over 384 CTAs.
#define GU_SMEM ((2*128*AST + 2*64*AST)*2)
__global__ void __launch_bounds__(256) k_gemm_u(const float* __restrict__ fc1w,
                                                const float* __restrict__ z) {
    extern __shared__ __align__(16) char smem_raw[];
    __nv_bfloat16* Ah = (__nv_bfloat16*)smem_raw;        // [128][AST]
    __nv_bfloat16* Al = Ah + 128*AST;
    __nv_bfloat16* Bh = Al + 128*AST;                    // [64][AST] (Bs[t][k] = z[t][k])
    __nv_bfloat16* Bl = Bh + 64*AST;
    const int tid = threadIdx.x;
    const int w = tid >> 5, lane = tid & 31;
    const int qr = lane >> 2, qc = lane & 3;
    float acc[8][4];
    #pragma unroll
    for (int nt = 0; nt < 8; nt++)
        #pragma unroll
        for (int i = 0; i < 4; i++) acc[nt][i] = 0.f;

    const int kbase = blockIdx.x * KPC;
    for (int ch = 0; ch < NCHUNK; ch++) {
        const int kg = kbase + ch*KC;
        __syncthreads();
        for (int i = tid; i < 128*32; i += 256) {         // A: 128 rows x 32 float2
            int r = i >> 5, c2 = i & 31;
            float2 v = *(const float2*)(fc1w + r*K2 + kg + 2*c2);
            uint32_t h, l; split_bf2(v, h, l);
            *(uint32_t*)(Ah + r*AST + 2*c2) = h;
            *(uint32_t*)(Al + r*AST + 2*c2) = l;
        }
        for (int i = tid; i < 64*32; i += 256) {          // B: z, 64 t x 32 float2
            int tt = i >> 5, c2 = i & 31;
            float2 v = *(const float2*)(z + tt*NF + kg + 2*c2);
            uint32_t h, l; split_bf2(v, h, l);
            *(uint32_t*)(Bh + tt*AST + 2*c2) = h;
            *(uint32_t*)(Bl + tt*AST + 2*c2) = l;
        }
        __syncthreads();
        #pragma unroll
        for (int ks = 0; ks < 4; ks++) {
            const int kk = ks*16;
            const int r0 = 16*w + qr;
            uint32_t ah[4], al[4];
            ah[0] = *(const uint32_t*)(Ah + r0*AST + kk + 2*qc);
            ah[1] = *(const uint32_t*)(Ah + (r0+8)*AST + kk + 2*qc);
            ah[2] = *(const uint32_t*)(Ah + r0*AST + kk + 2*qc + 8);
            ah[3] = *(const uint32_t*)(Ah + (r0+8)*AST + kk + 2*qc + 8);
            al[0] = *(const uint32_t*)(Al + r0*AST + kk + 2*qc);
            al[1] = *(const uint32_t*)(Al + (r0+8)*AST + kk + 2*qc);
            al[2] = *(const uint32_t*)(Al + r0*AST + kk + 2*qc + 8);
            al[3] = *(const uint32_t*)(Al + (r0+8)*AST + kk + 2*qc + 8);
            #pragma unroll
            for (int nt = 0; nt < 8; nt++) {
                const int cn = 8*nt + qr;
                uint32_t bh0 = *(const uint32_t*)(Bh + cn*AST + kk + 2*qc);
                uint32_t bh1 = *(const uint32_t*)(Bh + cn*AST + kk + 2*qc + 8);
                uint32_t bl0 = *(const uint32_t*)(Bl + cn*AST + kk + 2*qc);
                uint32_t bl1 = *(const uint32_t*)(Bl + cn*AST + kk + 2*qc + 8);
                MMA_BF16(acc[nt], ah, bh0, bh1);
                MMA_BF16(acc[nt], ah, bl0, bl1);
                MMA_BF16(acc[nt], al, bh0, bh1);
            }
        }
    }
    const int r0 = 16*w + qr;
    #pragma unroll
    for (int nt = 0; nt < 8; nt++) {
        const int t0 = 8*nt + 2*qc;
        atomicAdd(&g_U[t0*HD + r0],           acc[nt][0]);
        atomicAdd(&g_U[(t0+1)*HD + r0],       acc[nt][1]);
        atomicAdd(&g_U[t0*HD + r0 + 8],       acc[nt][2]);
        atomicAdd(&g_U[(t0+1)*HD + r0 + 8],   acc[nt][3]);
    }
}

// ------- GEMM 2 (bf16-split mma): M[128x128] = W_p[128,K] * fc2_w[K,128]
//         (+ fp32 side-dots: v = W_p@fc2_b, w0 = W_p@pg0) -------
#define GM_SMEM ((2*128*AST + 2*128*AST)*2 + 128*4)
__global__ void __launch_bounds__(256) k_gemm_m(const float* __restrict__ fc1w,
                                                const float* __restrict__ fc2w,
                                                const float* __restrict__ fc2b,
                                                const float* __restrict__ pg0) {
    extern __shared__ __align__(16) char smem_raw[];
    __nv_bfloat16* Ah = (__nv_bfloat16*)smem_raw;        // [128][AST]  W_p rows
    __nv_bfloat16* Al = Ah + 128*AST;
    __nv_bfloat16* Bh = Al + 128*AST;                    // [128 n][AST k]  Bs[n][k]=fc2w[k][n]
    __nv_bfloat16* Bl = Bh + 128*AST;
    float* Es = (float*)(Bl + 128*AST);                  // [128]: fc2b chunk | pg0 chunk
    const int tid = threadIdx.x;
    const int w = tid >> 5, lane = tid & 31;
    const int qr = lane >> 2, qc = lane & 3;
    const int erow = tid & 127, ewhich = tid >> 7;
    float acc[16][4];
    float accE = 0.f;
    #pragma unroll
    for (int nt = 0; nt < 16; nt++)
        #pragma unroll
        for (int i = 0; i < 4; i++) acc[nt][i] = 0.f;

    const int kbase = blockIdx.x * KPC;
    for (int ch = 0; ch < NCHUNK; ch++) {
        const int kg = kbase + ch*KC;
        __syncthreads();
        for (int i = tid; i < 128*32; i += 256) {         // A = W_p (second half of fc1w rows)
            int r = i >> 5, c2 = i & 31;
            float2 v = *(const float2*)(fc1w + r*K2 + NF + kg + 2*c2);
            uint32_t h, l; split_bf2(v, h, l);
            *(uint32_t*)(Ah + r*AST + 2*c2) = h;
            *(uint32_t*)(Al + r*AST + 2*c2) = l;
        }
        for (int i = tid; i < 64*128; i += 256) {         // B: transpose-store fc2w
            int n = i & 127, k = i >> 7;
            float x = fc2w[(kg + k)*HD + n];
            __nv_bfloat16 hb = __float2bfloat16(x);
            Bh[n*AST + k] = hb;
            Bl[n*AST + k] = __float2bfloat16(x - __bfloat162float(hb));
        }
        if (tid < 128) Es[tid] = (tid < 64) ? fc2b[kg + tid] : pg0[kg + tid - 64];
        __syncthreads();
        #pragma unroll
        for (int ks = 0; ks < 4; ks++) {
            const int kk = ks*16;
            const int r0 = 16*w + qr;
            uint32_t ah[4], al[4];
            ah[0] = *(const uint32_t*)(Ah + r0*AST + kk + 2*qc);
            ah[1] = *(const uint32_t*)(Ah + (r0+8)*AST + kk + 2*qc);
            ah[2] = *(const uint32_t*)(Ah + r0*AST + kk + 2*qc + 8);
            ah[3] = *(const uint32_t*)(Ah + (r0+8)*AST + kk + 2*qc + 8);
            al[0] = *(const uint32_t*)(Al + r0*AST + kk + 2*qc);
            al[1] = *(const uint32_t*)(Al + (r0+8)*AST + kk + 2*qc);
            al[2] = *(const uint32_t*)(Al + r0*AST + kk + 2*qc + 8);
            al[3] = *(const uint32_t*)(Al + (r0+8)*AST + kk + 2*qc + 8);
            #pragma unroll
            for (int nt = 0; nt < 16; nt++) {
                const int cn = 8*nt + qr;
                uint32_t bh0 = *(const uint32_t*)(Bh + cn*AST + kk + 2*qc);
                uint32_t bh1 = *(const uint32_t*)(Bh + cn*AST + kk + 2*qc + 8);
                uint32_t bl0 = *(const uint32_t*)(Bl + cn*AST + kk + 2*qc);
                uint32_t bl1 = *(const uint32_t*)(Bl + cn*AST + kk + 2*qc + 8);
                MMA_BF16(acc[nt], ah, bh0, bh1);
                MMA_BF16(acc[nt], ah, bl0, bl1);
                MMA_BF16(acc[nt], al, bh0, bh1);
            }
        }
        // side dots in fp32 (A reconstructed = hi+lo, err ~2^-18)
        #pragma unroll 8
        for (int k = 0; k < KC; k++) {
            float a = __bfloat162float(Ah[erow*AST + k]) + __bfloat162float(Al[erow*AST + k]);
            accE += a * Es[ewhich*64 + k];
        }
    }
    const int r0 = 16*w + qr;
    #pragma unroll
    for (int nt = 0; nt < 16; nt++) {
        const int c0 = 8*nt + 2*qc;
        atomicAdd(&g_M[r0*HD + c0],           acc[nt][0]);
        atomicAdd(&g_M[r0*HD + c0 + 1],       acc[nt][1]);
        atomicAdd(&g_M[(r0+8)*HD + c0],       acc[nt][2]);
        atomicAdd(&g_M[(r0+8)*HD + c0 + 1],   acc[nt][3]);
    }
    atomicAdd(ewhich ? &g_w0[erow] : &g_v[erow], accE);
}

// ---------------- Phase 2: cluster-resident recurrent scan (R7 273us version) ----------------
#define OFS_WI1 0
#define OFS_WH1 8192
#define OFS_WI2 16384
#define OFS_WH2 24576
#define OFS_M   32768
#define OFS_U   34816
#define OFS_X   35840
#define OFS_H1  35968   /* 2 x 128 */
#define OFS_H2  36224   /* 2 x 128 */
#define OFS_G   36480
#define OFS_B1  36544
#define OFS_B2  36608
#define OFS_XB  36672
#define OFS_XB0 36688
#define OFS_C1  36704
#define OFS_C2  36720
#define SCAN_SMEM_FLOATS 36736
#define SCAN_SMEM_BYTES  (SCAN_SMEM_FLOATS*4)

__global__ void __launch_bounds__(256, 1) __cluster_dims__(CL, 1, 1)
k_scan(const float* __restrict__ h1_in, const float* __restrict__ c1_in,
       const float* __restrict__ h2_in, const float* __restrict__ c2_in,
       const float* __restrict__ fc1b,
       const float* __restrict__ wih1, const float* __restrict__ whh1,
       const float* __restrict__ bih1, const float* __restrict__ bhh1,
       const float* __restrict__ wih2, const float* __restrict__ whh2,
       const float* __restrict__ bih2, const float* __restrict__ bhh2,
       float* __restrict__ out, int out_size)
{
    extern __shared__ __align__(16) float sm[];
    const int tid  = threadIdx.x;
    const int warp = tid >> 5, lane = tid & 31;
    const uint32_t rank = ctarank();
    const uint32_t sbase = smem_u32(sm);

    for (int idx = tid; idx < 64*128; idx += 256) {
        int l = idx >> 7, k = idx & 127;
        int gr = ((l >> 4) << 7) + (int)rank*16 + (l & 15);
        sm[OFS_WI1 + idx] = wih1[gr*HD + k];
        sm[OFS_WH1 + idx] = whh1[gr*HD + k];
        sm[OFS_WI2 + idx] = wih2[gr*HD + k];
        sm[OFS_WH2 + idx] = whh2[gr*HD + k];
    }
    for (int idx = tid; idx < 16*128; idx += 256) {
        int l = idx >> 7, k = idx & 127;
        sm[OFS_M + idx] = g_M[((int)rank*16 + l)*HD + k];
    }
    for (int idx = tid; idx < S*16; idx += 256) {
        int t = idx >> 4, j = idx & 15;
        sm[OFS_U + idx] = g_U[t*HD + (int)rank*16 + j];
    }
    if (tid < 64) {
        int gr = ((tid >> 4) << 7) + (int)rank*16 + (tid & 15);
        sm[OFS_B1 + tid] = bih1[gr] + bhh1[gr];
        sm[OFS_B2 + tid] = bih2[gr] + bhh2[gr];
    }
    if (tid < 16) {
        int e = (int)rank*16 + tid;
        sm[OFS_XB  + tid] = fc1b[e] + g_v[e];
        sm[OFS_XB0 + tid] = fc1b[e] + g_w0[e];
        sm[OFS_C1  + tid] = c1_in[e];
        sm[OFS_C2  + tid] = c2_in[e];
    }
    if (tid < HD) {
        sm[OFS_H1 + tid] = h1_in[tid];
        sm[OFS_H2 + tid] = h2_in[tid];
    }
    __syncthreads();
    CLUSTER_BAR();

    for (int t = 0; t < S; t++) {
        const int p = t & 1;

        if (t == 0) {
            if (tid < 16)
                sm[OFS_X + (int)rank*16 + tid] = fmaxf(sm[OFS_U + tid] + sm[OFS_XB0 + tid], 0.f);
        } else {
            float4 hv = ((const float4*)(sm + OFS_H2 + p*HD))[lane];
            #pragma unroll
            for (int ii = 0; ii < 2; ii++) {
                int l = warp*2 + ii;
                float4 m = ((const float4*)(sm + OFS_M + l*HD))[lane];
                float pd = m.x*hv.x + m.y*hv.y + m.z*hv.z + m.w*hv.w;
                #pragma unroll
                for (int off = 16; off; off >>= 1) pd += __shfl_xor_sync(0xffffffffu, pd, off);
                if (lane == 0)
                    sm[OFS_X + (int)rank*16 + l] = fmaxf(pd + sm[OFS_U + t*16 + l] + sm[OFS_XB + l], 0.f);
            }
        }
        __syncthreads();
        if (tid < 128) {
            int e = (int)rank*16 + (tid >> 3);
            st_cluster(mapa_u32(sbase + (uint32_t)(OFS_X + e)*4u, (uint32_t)(tid & 7)), sm[OFS_X + e]);
        }
        CLUSTER_BAR();

        {
            float4 xv = ((const float4*)(sm + OFS_X))[lane];
            float4 hv = ((const float4*)(sm + OFS_H1 + p*HD))[lane];
            #pragma unroll
            for (int i = 0; i < 8; i++) {
                int l = warp*8 + i;
                float4 wi = ((const float4*)(sm + OFS_WI1 + l*HD))[lane];
                float4 wh = ((const float4*)(sm + OFS_WH1 + l*HD))[lane];
                float pd = wi.x*xv.x + wi.y*xv.y + wi.z*xv.z + wi.w*xv.w
                         + wh.x*hv.x + wh.y*hv.y + wh.z*hv.z + wh.w*hv.w;
                #pragma unroll
                for (int off = 16; off; off >>= 1) pd += __shfl_xor_sync(0xffffffffu, pd, off);
                if (lane == 0) sm[OFS_G + l] = pd + sm[OFS_B1 + l];
            }
        }
        __syncthreads();
        if (tid < 16) {
            float gi = sm[OFS_G + tid],      gf = sm[OFS_G + 16 + tid];
            float gg = sm[OFS_G + 32 + tid], go = sm[OFS_G + 48 + tid];
            float c = sigm(gf)*sm[OFS_C1 + tid] + sigm(gi)*tanhf(gg);
            sm[OFS_C1 + tid] = c;
            sm[OFS_H1 + (p^1)*HD + (int)rank*16 + tid] = sigm(go)*tanhf(c);
        }
        __syncthreads();
        if (tid < 128) {
            int e = (int)rank*16 + (tid >> 3);
            st_cluster(mapa_u32(sbase + (uint32_t)(OFS_H1 + (p^1)*HD + e)*4u, (uint32_t)(tid & 7)),
                       sm[OFS_H1 + (p^1)*HD + e]);
        }
        CLUSTER_BAR();

        {
            float4 xv = ((const float4*)(sm + OFS_H1 + (p^1)*HD))[lane];
            float4 hv = ((const float4*)(sm + OFS_H2 + p*HD))[lane];
            #pragma unroll
            for (int i = 0; i < 8; i++) {
                int l = warp*8 + i;
                float4 wi = ((const float4*)(sm + OFS_WI2 + l*HD))[lane];
                float4 wh = ((const float4*)(sm + OFS_WH2 + l*HD))[lane];
                float pd = wi.x*xv.x + wi.y*xv.y + wi.z*xv.z + wi.w*xv.w
                         + wh.x*hv.x + wh.y*hv.y + wh.z*hv.z + wh.w*hv.w;
                #pragma unroll
                for (int off = 16; off; off >>= 1) pd += __shfl_xor_sync(0xffffffffu, pd, off);
                if (lane == 0) sm[OFS_G + l] = pd + sm[OFS_B2 + l];
            }
        }
        __syncthreads();
        if (tid < 16) {
            float gi = sm[OFS_G + tid],      gf = sm[OFS_G + 16 + tid];
            float gg = sm[OFS_G + 32 + tid], go = sm[OFS_G + 48 + tid];
            float c = sigm(gf)*sm[OFS_C2 + tid] + sigm(gi)*tanhf(gg);
            sm[OFS_C2 + tid] = c;
            float h = sigm(go)*tanhf(c);
            int e = (int)rank*16 + tid;
            sm[OFS_H2 + (p^1)*HD + e] = h;
            g_H2T[e*S + t] = h;
        }
        __syncthreads();
        if (tid < 128) {
            int e = (int)rank*16 + (tid >> 3);
            st_cluster(mapa_u32(sbase + (uint32_t)(OFS_H2 + (p^1)*HD + e)*4u, (uint32_t)(tid & 7)),
                       sm[OFS_H2 + (p^1)*HD + e]);
        }
        CLUSTER_BAR();
    }

    if (out_size >= S*NF + 4*HD && tid < 16) {
        int e = (int)rank*16 + tid;
        out[S*NF + 0*HD + e] = sm[OFS_H1 + e];
        out[S*NF + 1*HD + e] = sm[OFS_C1 + tid];
        out[S*NF + 2*HD + e] = sm[OFS_H2 + e];
        out[S*NF + 3*HD + e] = sm[OFS_C2 + tid];
    }
}

// ------- GEMM 3 (f32x2): out[t,k] = fc2_w[k,:] . h2_t + fc2_b[k] + y[t,k] -------
__global__ void __launch_bounds__(256) k_out(const float* __restrict__ fc2w,
                                             const float* __restrict__ fc2b,
                                             const float* __restrict__ y,
                                             float* __restrict__ out) {
    __shared__ __align__(16) float H2T[HD*S];
    int tid = threadIdx.x;
    for (int i = tid; i < HD*S; i += 256) H2T[i] = g_H2T[i];
    __syncthreads();

    int k = blockIdx.x*256 + tid;
    const float4* w4 = (const float4*)(fc2w + k*HD);
    unsigned long long acc2[32];
    #pragma unroll
    for (int i = 0; i < 32; i++) acc2[i] = 0ull;

    #pragma unroll 2
    for (int j4 = 0; j4 < 32; j4++) {
        float4 w = w4[j4];
        float wc[4] = {w.x, w.y, w.z, w.w};
        #pragma unroll
        for (int cc = 0; cc < 4; cc++) {
            unsigned long long pw = pack2(wc[cc]);
            int j = j4*4 + cc;
            const ulonglong2* hp = (const ulonglong2*)(H2T + j*S);
            #pragma unroll
            for (int tq = 0; tq < 16; tq++) {
                ulonglong2 hh = hp[tq];
                fma2(acc2[2*tq],     pw, hh.x);
                fma2(acc2[2*tq + 1], pw, hh.y);
            }
        }
    }
    float b = fc2b[k];
    #pragma unroll 4
    for (int i = 0; i < 32; i++) {
        int t0 = 2*i;
        out[t0*NF + k]       = lo2(acc2[i]) + b + y[t0*NF + k];
        out[(t0 + 1)*NF + k] = hi2(acc2[i]) + b + y[(t0 + 1)*NF + k];
    }
}

// ---------------- launcher ----------------
extern "C" void kernel_launch(void* const* d_in, const int* in_sizes, int n_in,
                              void* d_out, int out_size) {
    const float* z    = (const float*)d_in[0];
    const float* y    = (const float*)d_in[1];
    const float* pg0  = (const float*)d_in[2];
    const float* h1   = (const float*)d_in[3];
    const float* c1   = (const float*)d_in[4];
    const float* h2   = (const float*)d_in[5];
    const float* c2   = (const float*)d_in[6];
    const float* fc1w = (const float*)d_in[7];
    const float* fc1b = (const float*)d_in[8];
    const float* wih1 = (const float*)d_in[9];
    const float* whh1 = (const float*)d_in[10];
    const float* bih1 = (const float*)d_in[11];
    const float* bhh1 = (const float*)d_in[12];
    const float* wih2 = (const float*)d_in[13];
    const float* whh2 = (const float*)d_in[14];
    const float* bih2 = (const float*)d_in[15];
    const float* bhh2 = (const float*)d_in[16];
    const float* fc2w = (const float*)d_in[17];
    const float* fc2b = (const float*)d_in[18];
    float* out = (float*)d_out;

    cudaFuncSetAttribute(k_scan,   cudaFuncAttributeMaxDynamicSharedMemorySize, SCAN_SMEM_BYTES);
    cudaFuncSetAttribute(k_gemm_u, cudaFuncAttributeMaxDynamicSharedMemorySize, GU_SMEM);
    cudaFuncSetAttribute(k_gemm_m, cudaFuncAttributeMaxDynamicSharedMemorySize, GM_SMEM);

    k_zero<<<32, 256>>>();
    k_gemm_u<<<G_CTAS, 256, GU_SMEM>>>(fc1w, z);
    k_gemm_m<<<G_CTAS, 256, GM_SMEM>>>(fc1w, fc2w, fc2b, pg0);
    k_scan<<<CL, 256, SCAN_SMEM_BYTES>>>(h1, c1, h2, c2, fc1b,
                                         wih1, whh1, bih1, bhh1,
                                         wih2, whh2, bih2, bhh2,
                                         out, out_size);
    k_out<<<768, 256>>>(fc2w, fc2b, y, out);
}